// round 5
// baseline (speedup 1.0000x reference)
#include <cuda_runtime.h>
#include <cstdint>

#define BB 32
#define LL 128
#define FF 128
#define RR 4096
#define HH (RR >> 1)
#define NN 262144
#define NGROUPS (BB * RR)      // 131072
#define CAP 32                 // Poisson(2) per group; overflow clamped (prob ~1e-27)

// Scratch (allocation-free: __device__ globals).
__device__ int    g_cnt[NGROUPS];
__device__ int    g_slots[NGROUPS * CAP];
__device__ float4 g_cw[NN];    // per-element fused coeffs (d0w0, d1w1, d2w2, d2w3)

__device__ __forceinline__ void acc_fma(float4& a, float c, const float4& v) {
    a.x = fmaf(c, v.x, a.x); a.y = fmaf(c, v.y, a.y);
    a.z = fmaf(c, v.z, a.z); a.w = fmaf(c, v.w, a.w);
}

// ---------------------------------------------------------------------------
// Kernel 1: one thread per element — fused coefficients + inverted index.
__global__ void dti_build_kernel(const float4* __restrict__ arg_w,  // (B*L) float4
                                 const float*  __restrict__ op_dist,
                                 const int* __restrict__ batch_idx,
                                 const int* __restrict__ slot_idx,
                                 const int* __restrict__ role_idx,
                                 int n) {
    int e = blockIdx.x * blockDim.x + threadIdx.x;
    if (e >= n) return;
    int b = __ldg(batch_idx + e);
    int s = __ldg(slot_idx + e);
    int j = __ldg(role_idx + e);
    float4 w = __ldg(arg_w + b * LL + s);
    float d0 = __ldg(op_dist + b * 3 + 0);
    float d1 = __ldg(op_dist + b * 3 + 1);
    float d2 = __ldg(op_dist + b * 3 + 2);
    g_cw[e] = make_float4(d0 * w.x, d1 * w.y, d2 * w.z, d2 * w.w);
    int key = (b << 12) + j;
    int pos = atomicAdd(&g_cnt[key], 1);
    if (pos < CAP) g_slots[key * CAP + pos] = e;
}

// ---------------------------------------------------------------------------
// Kernel 2: ONE WARP PER OUTPUT ROW. Lane l owns features [4l, 4l+4).
// Row r = (b, rr) receives:
//   cons : group (rr>>1), coeff (rr even ? cw.z : cw.w)   [all rows]
//   car  : group 2*rr,    coeff cw.x                      [rr < H]
//   cdr  : group 2*rr+1,  coeff cw.y                      [1 <= rr < H]
//   +d2*root_filler[b] at rr == 1
// Fused loop: each iteration issues loads for 2 elements of each live group
// (up to 12 independent LDGs) before any FMA consumes them.
__global__ __launch_bounds__(256)
void dti_gather_row_kernel(const float4* __restrict__ mem,
                           const float4* __restrict__ root_filler,
                           const float*  __restrict__ op_dist,
                           float4* __restrict__ out) {
    int r = (blockIdx.x * blockDim.x + threadIdx.x) >> 5;   // global row id
    int lane = threadIdx.x & 31;
    int b = r >> 12;
    int rr = r & (RR - 1);
    int gbase = b << 12;

    // ---- all index/slot loads issued up front (independent) ----
    int gc = gbase + (rr >> 1);
    int cntc = min(__ldg(&g_cnt[gc]), CAP);
    int svc = __ldg(&g_slots[gc * CAP + lane]);             // 128B coalesced

    bool low = (rr < HH);
    int cnta = 0, cntb = 0, sva = 0, svb = 0;
    if (low) {
        int2 c2 = __ldg((const int2*)&g_cnt[gbase + 2 * rr]);   // 8B aligned
        cnta = min(c2.x, CAP);
        cntb = (rr == 0) ? 0 : min(c2.y, CAP);              // cdr excludes role 1
        int sb = (gbase + 2 * rr) * CAP;
        sva = __ldg(&g_slots[sb + lane]);
        svb = __ldg(&g_slots[sb + CAP + lane]);
    }

    bool even = !(rr & 1);
    float4 a = make_float4(0.f, 0.f, 0.f, 0.f);

    int mx = max(cntc, max(cnta, cntb));
    for (int i = 0; i < mx; i += 2) {
        // -------- load phase: everything independent --------
        float4 cc0, vc0, cc1, vc1, ca0, va0, ca1, va1, cb0, vb0, cb1, vb1;
        bool hc0 = (i < cntc),     hc1 = (i + 1 < cntc);
        bool ha0 = (i < cnta),     ha1 = (i + 1 < cnta);
        bool hb0 = (i < cntb),     hb1 = (i + 1 < cntb);
        int ec0 = __shfl_sync(0xffffffffu, svc, i & 31);
        int ec1 = __shfl_sync(0xffffffffu, svc, (i + 1) & 31);
        int ea0 = __shfl_sync(0xffffffffu, sva, i & 31);
        int ea1 = __shfl_sync(0xffffffffu, sva, (i + 1) & 31);
        int eb0 = __shfl_sync(0xffffffffu, svb, i & 31);
        int eb1 = __shfl_sync(0xffffffffu, svb, (i + 1) & 31);
        if (hc0) { cc0 = __ldg(&g_cw[ec0]); vc0 = __ldg(mem + (size_t)ec0 * (FF/4) + lane); }
        if (ha0) { ca0 = __ldg(&g_cw[ea0]); va0 = __ldg(mem + (size_t)ea0 * (FF/4) + lane); }
        if (hb0) { cb0 = __ldg(&g_cw[eb0]); vb0 = __ldg(mem + (size_t)eb0 * (FF/4) + lane); }
        if (hc1) { cc1 = __ldg(&g_cw[ec1]); vc1 = __ldg(mem + (size_t)ec1 * (FF/4) + lane); }
        if (ha1) { ca1 = __ldg(&g_cw[ea1]); va1 = __ldg(mem + (size_t)ea1 * (FF/4) + lane); }
        if (hb1) { cb1 = __ldg(&g_cw[eb1]); vb1 = __ldg(mem + (size_t)eb1 * (FF/4) + lane); }
        // -------- consume phase --------
        if (hc0) acc_fma(a, even ? cc0.z : cc0.w, vc0);
        if (ha0) acc_fma(a, ca0.x, va0);
        if (hb0) acc_fma(a, cb0.y, vb0);
        if (hc1) acc_fma(a, even ? cc1.z : cc1.w, vc1);
        if (ha1) acc_fma(a, ca1.x, va1);
        if (hb1) acc_fma(a, cb1.y, vb1);
    }

    if (rr == 1) {   // row 1: += d2 * root_filler[b]
        float d2 = __ldg(op_dist + b * 3 + 2);
        float4 rf = __ldg(root_filler + b * (FF / 4) + lane);
        acc_fma(a, d2, rf);
    }

    // One streaming store per row; output never re-read.
    __stcs(out + (size_t)r * (FF / 4) + lane, a);
}

// ---------------------------------------------------------------------------
extern "C" void kernel_launch(void* const* d_in, const int* in_sizes, int n_in,
                              void* d_out, int out_size) {
    const float* mem = (const float*)d_in[0];
    const float* aw  = (const float*)d_in[1];
    const float* rf  = (const float*)d_in[2];
    const float* od  = (const float*)d_in[3];
    const int* bi    = (const int*)d_in[4];
    const int* si    = (const int*)d_in[5];
    const int* ri    = (const int*)d_in[6];
    float4* out      = (float4*)d_out;

    int n = in_sizes[4];  // N elements

    // 1. zero counters via memset node (0.5 MB)
    void* cnt_ptr = nullptr;
    cudaGetSymbolAddress(&cnt_ptr, g_cnt);
    cudaMemsetAsync(cnt_ptr, 0, NGROUPS * sizeof(int), 0);

    // 2. coefficients + inverted index
    dti_build_kernel<<<(n + 255) / 256, 256>>>((const float4*)aw, od, bi, si, ri, n);

    // 3. gather: one warp per row: B*R = 131072 warps -> 16384 blocks x 256
    dti_gather_row_kernel<<<(BB * RR) * 32 / 256, 256>>>(
        (const float4*)mem, (const float4*)rf, od, out);
}

// round 6
// speedup vs baseline: 1.4548x; 1.4548x over previous
#include <cuda_runtime.h>
#include <cstdint>

#define BB 32
#define LL 128
#define FF 128
#define RR 4096
#define HH (RR >> 1)
#define NN 262144
#define NGROUPS (BB * RR)      // 131072
#define CAP 32                 // Poisson(2); overflow clamped (prob ~1e-27)

// Scratch (allocation-free: __device__ globals).
__device__ int    g_cnt[NGROUPS];
__device__ int    g_slots[NGROUPS * CAP];
__device__ float4 g_cw[NN];    // fused coeffs (d0w0, d1w1, d2w2, d2w3)

__device__ __forceinline__ void acc_fma(float4& a, float c, const float4& v) {
    a.x = fmaf(c, v.x, a.x); a.y = fmaf(c, v.y, a.y);
    a.z = fmaf(c, v.z, a.z); a.w = fmaf(c, v.w, a.w);
}

// ---------------------------------------------------------------------------
// Kernel 1: one thread per element — fused coefficients + inverted index.
__global__ void dti_build_kernel(const float4* __restrict__ arg_w,
                                 const float*  __restrict__ op_dist,
                                 const int* __restrict__ batch_idx,
                                 const int* __restrict__ slot_idx,
                                 const int* __restrict__ role_idx,
                                 int n) {
    int e = blockIdx.x * blockDim.x + threadIdx.x;
    if (e >= n) return;
    int b = __ldg(batch_idx + e);
    int s = __ldg(slot_idx + e);
    int j = __ldg(role_idx + e);
    float4 w = __ldg(arg_w + b * LL + s);
    float d0 = __ldg(op_dist + b * 3 + 0);
    float d1 = __ldg(op_dist + b * 3 + 1);
    float d2 = __ldg(op_dist + b * 3 + 2);
    g_cw[e] = make_float4(d0 * w.x, d1 * w.y, d2 * w.z, d2 * w.w);
    int key = (b << 12) + j;
    int pos = atomicAdd(&g_cnt[key], 1);
    if (pos < CAP) g_slots[key * CAP + pos] = e;
}

// ---------------------------------------------------------------------------
// Strip-2 accumulate of one group into one accumulator.
// sel: 0 -> cw.x (car), 1 -> cw.y (cdr), 2 -> cw.z (cons even), 3 -> cw.w (cons odd)
__device__ __forceinline__ void gacc(const float4* __restrict__ mem,
                                     int lane, int sv, int cnt, int sel, float4& a) {
    #pragma unroll 1
    for (int i = 0; i < cnt; i += 2) {
        int e0 = __shfl_sync(0xffffffffu, sv, i);
        int e1 = __shfl_sync(0xffffffffu, sv, (i + 1) & 31);
        float4 c0 = __ldg(&g_cw[e0]);
        float4 v0 = __ldg(mem + (size_t)e0 * (FF / 4) + lane);
        bool h1 = (i + 1 < cnt);
        float4 c1, v1;
        if (h1) {
            c1 = __ldg(&g_cw[e1]);
            v1 = __ldg(mem + (size_t)e1 * (FF / 4) + lane);
        }
        float co0 = (sel & 2) ? ((sel & 1) ? c0.w : c0.z) : ((sel & 1) ? c0.y : c0.x);
        acc_fma(a, co0, v0);
        if (h1) {
            float co1 = (sel & 2) ? ((sel & 1) ? c1.w : c1.z) : ((sel & 1) ? c1.y : c1.x);
            acc_fma(a, co1, v1);
        }
    }
}

// ---------------------------------------------------------------------------
// Kernel 2: ALL output rows, no atomics, no init pass.
//   warps [0, 65536):        one warp per LOW row (b, rr<H):
//        out = cons(group rr>>1, sel 2/3) + car(group 2rr, sel 0)
//            + cdr(group 2rr+1, sel 1, skip rr==0) + rf at rr==1
//   warps [65536, 98304):    one warp per HIGH row PAIR (b, rows 2k/2k+1, k>=H/2):
//        rows get cons only, both from group k (elements read once).
__global__ __launch_bounds__(256)
void dti_out_kernel(const float4* __restrict__ mem,
                    const float4* __restrict__ root_filler,
                    const float*  __restrict__ op_dist,
                    float4* __restrict__ out) {
    int wid = (blockIdx.x * blockDim.x + threadIdx.x) >> 5;
    int lane = threadIdx.x & 31;

    if (wid < BB * HH) {
        // ---------------- low row: rr in [0, H) ----------------
        int b = wid >> 11;                 // H = 2048 rows per batch
        int rr = wid & (HH - 1);
        int gbase = b << 12;

        // all index loads issued up front (independent)
        int gc = gbase + (rr >> 1);
        int cntc = min(__ldg(&g_cnt[gc]), CAP);
        int svc = __ldg(&g_slots[gc * CAP + lane]);
        int2 c2 = __ldg((const int2*)&g_cnt[gbase + 2 * rr]);
        int sb = (gbase + 2 * rr) * CAP;
        int sva = __ldg(&g_slots[sb + lane]);
        int svb = __ldg(&g_slots[sb + CAP + lane]);
        int cnta = min(c2.x, CAP);
        int cntb = (rr == 0) ? 0 : min(c2.y, CAP);

        float4 a = make_float4(0.f, 0.f, 0.f, 0.f);
        gacc(mem, lane, svc, cntc, 2 | (rr & 1), a);   // cons
        gacc(mem, lane, sva, cnta, 0, a);              // car
        gacc(mem, lane, svb, cntb, 1, a);              // cdr

        if (rr == 1) {
            float d2 = __ldg(op_dist + b * 3 + 2);
            float4 rf = __ldg(root_filler + b * (FF / 4) + lane);
            acc_fma(a, d2, rf);
        }
        __stcs(out + ((size_t)(gbase + rr)) * (FF / 4) + lane, a);
    } else {
        // ---------------- high pair: rows 2k, 2k+1, k in [H/2, H) ----------------
        int t = wid - BB * HH;
        int b = t >> 10;                   // H/2 = 1024 pairs per batch
        int k = (HH / 2) + (t & 1023);
        int g = (b << 12) + k;
        int cnt = min(__ldg(&g_cnt[g]), CAP);
        int sv = __ldg(&g_slots[g * CAP + lane]);

        float4 a0 = make_float4(0.f, 0.f, 0.f, 0.f);
        float4 a1 = make_float4(0.f, 0.f, 0.f, 0.f);
        #pragma unroll 1
        for (int i = 0; i < cnt; i += 2) {
            int e0 = __shfl_sync(0xffffffffu, sv, i);
            int e1 = __shfl_sync(0xffffffffu, sv, (i + 1) & 31);
            float4 c0 = __ldg(&g_cw[e0]);
            float4 v0 = __ldg(mem + (size_t)e0 * (FF / 4) + lane);
            bool h1 = (i + 1 < cnt);
            float4 c1, v1;
            if (h1) {
                c1 = __ldg(&g_cw[e1]);
                v1 = __ldg(mem + (size_t)e1 * (FF / 4) + lane);
            }
            acc_fma(a0, c0.z, v0); acc_fma(a1, c0.w, v0);
            if (h1) { acc_fma(a0, c1.z, v1); acc_fma(a1, c1.w, v1); }
        }
        size_t o = ((size_t)((b << 12) + 2 * k)) * (FF / 4) + lane;
        __stcs(out + o, a0);
        __stcs(out + o + (FF / 4), a1);
    }
}

// ---------------------------------------------------------------------------
extern "C" void kernel_launch(void* const* d_in, const int* in_sizes, int n_in,
                              void* d_out, int out_size) {
    const float* mem = (const float*)d_in[0];
    const float* aw  = (const float*)d_in[1];
    const float* rf  = (const float*)d_in[2];
    const float* od  = (const float*)d_in[3];
    const int* bi    = (const int*)d_in[4];
    const int* si    = (const int*)d_in[5];
    const int* ri    = (const int*)d_in[6];
    float4* out      = (float4*)d_out;

    int n = in_sizes[4];

    void* cnt_ptr = nullptr;
    cudaGetSymbolAddress(&cnt_ptr, g_cnt);
    cudaMemsetAsync(cnt_ptr, 0, NGROUPS * sizeof(int), 0);

    dti_build_kernel<<<(n + 255) / 256, 256>>>((const float4*)aw, od, bi, si, ri, n);

    // 65536 low-row warps + 32768 high-pair warps = 98304 warps
    int total_warps = BB * HH + BB * (HH / 2);
    dti_out_kernel<<<total_warps * 32 / 256, 256>>>(
        (const float4*)mem, (const float4*)rf, od, out);
}